// round 1
// baseline (speedup 1.0000x reference)
#include <cuda_runtime.h>
#include <cuda_bf16.h>

// Problem constants
#define BB 4
#define SS 2048
#define HH 4
#define CC 64
#define DD 256          // H*C
#define WINR 10
#define WMAX 21         // 2*WINR+1
#define MROWS (BB*SS)   // 8192

// Scratch: 0=Qp 1=Kp 2=Vp 3=Gp 4=Att  (each [B*S, D] row-major)
__device__ float g_buf[5][MROWS * DD];

// ---------------------------------------------------------------------------
// Tiled fp32 GEMM: C[M,N] = A[M,K] @ B[K,N] (+bias) (optional sigmoid)
// BM=BN=64, BK=16, 256 threads, 4x4 register tile per thread.
// mode: 0 = plain, 1 = sigmoid(x + bias), 2 = x + bias
// aIdx : >=0 -> A = g_buf[aIdx], else A = Ain param
// outIdx: >=0 -> write g_buf[outIdx]; -1 -> write Cout param
// ---------------------------------------------------------------------------
__global__ void sgemm64(const float* __restrict__ Ain,
                        const float* __restrict__ Bw,
                        const float* __restrict__ bias,
                        float* __restrict__ Cout,
                        int aIdx, int outIdx, int mode)
{
    const int M = MROWS, N = DD, K = DD;
    __shared__ float As[16][64];   // [k][m]
    __shared__ float Bs[16][64];   // [k][n]

    const float* A = (aIdx >= 0) ? g_buf[aIdx] : Ain;
    float* C = (outIdx >= 0) ? g_buf[outIdx] : Cout;

    const int tid = threadIdx.x;
    const int m0 = blockIdx.y * 64;
    const int n0 = blockIdx.x * 64;
    const int tx = tid & 15;       // 0..15 -> n
    const int ty = tid >> 4;       // 0..15 -> m

    // load mapping
    const int lam = tid >> 2;          // 0..63 row (m) within A tile
    const int lak = (tid & 3) * 4;     // k offset (float4)
    const int lbk = tid >> 4;          // 0..15 row (k) within B tile
    const int lbn = (tid & 15) * 4;    // n offset (float4)

    float acc[4][4] = {};

    for (int k0 = 0; k0 < K; k0 += 16) {
        float4 a4 = *reinterpret_cast<const float4*>(&A[(m0 + lam) * K + k0 + lak]);
        As[lak + 0][lam] = a4.x;
        As[lak + 1][lam] = a4.y;
        As[lak + 2][lam] = a4.z;
        As[lak + 3][lam] = a4.w;
        float4 b4 = *reinterpret_cast<const float4*>(&Bw[(k0 + lbk) * N + n0 + lbn]);
        *reinterpret_cast<float4*>(&Bs[lbk][lbn]) = b4;
        __syncthreads();

#pragma unroll
        for (int k = 0; k < 16; ++k) {
            float ra[4], rb[4];
#pragma unroll
            for (int i = 0; i < 4; ++i) ra[i] = As[k][ty * 4 + i];
#pragma unroll
            for (int j = 0; j < 4; ++j) rb[j] = Bs[k][tx * 4 + j];
#pragma unroll
            for (int i = 0; i < 4; ++i)
#pragma unroll
                for (int j = 0; j < 4; ++j)
                    acc[i][j] += ra[i] * rb[j];
        }
        __syncthreads();
    }

#pragma unroll
    for (int i = 0; i < 4; ++i) {
        const int m = m0 + ty * 4 + i;
        float v[4];
#pragma unroll
        for (int j = 0; j < 4; ++j) {
            const int n = n0 + tx * 4 + j;
            float x = acc[i][j];
            if (mode >= 1) x += bias[n];
            if (mode == 1) x = 1.0f / (1.0f + __expf(-x));
            v[j] = x;
        }
        float4 v4;
        v4.x = v[0]; v4.y = v[1]; v4.z = v[2]; v4.w = v[3];
        *reinterpret_cast<float4*>(&C[m * N + n0 + tx * 4]) = v4;
    }
}

// ---------------------------------------------------------------------------
// Windowed attention + gating.
// Block: 256 threads, handles (b, h, 64 consecutive queries).
// smem K/V slab of 84 rows (union of the queries' windows), warp per query.
// Att[b,s,h*C+c] = (softmax_band(Q K^T / 8) @ V) * G
// ---------------------------------------------------------------------------
__global__ void attn_kernel(const unsigned char* __restrict__ mask)
{
    __shared__ float Ks[84][65];
    __shared__ float Vs[84][65];
    __shared__ float qs[8][64];
    __shared__ float ps[8][32];
    __shared__ int   kvalid[84];

    const float* __restrict__ Qp = g_buf[0];
    const float* __restrict__ Kp = g_buf[1];
    const float* __restrict__ Vp = g_buf[2];
    const float* __restrict__ Gp = g_buf[3];
    float* __restrict__ Att = g_buf[4];

    const int s0 = blockIdx.x * 64;
    const int h  = blockIdx.y;
    const int b  = blockIdx.z;
    const int hb = h * CC;
    const int tid = threadIdx.x;

    // cooperative slab load: rows j = s0-10 .. s0+73
    for (int idx = tid; idx < 84 * 64; idx += 256) {
        const int r = idx >> 6;
        const int c = idx & 63;
        const int j = s0 - WINR + r;
        float kv = 0.f, vv = 0.f;
        if (j >= 0 && j < SS) {
            const int g = (b * SS + j) * DD + hb + c;
            kv = Kp[g];
            vv = Vp[g];
        }
        Ks[r][c] = kv;
        Vs[r][c] = vv;
    }
    if (tid < 84) {
        const int j = s0 - WINR + tid;
        kvalid[tid] = (j >= 0 && j < SS && mask[b * SS + j] == 0) ? 1 : 0;
    }
    __syncthreads();

    const int w = tid >> 5;
    const int lane = tid & 31;

    for (int i = 0; i < 8; ++i) {
        const int sl = w * 8 + i;          // local query index 0..63
        const int s = s0 + sl;
        const int base = (b * SS + s) * DD + hb;

        qs[w][lane]      = Qp[base + lane];
        qs[w][lane + 32] = Qp[base + lane + 32];
        __syncwarp();

        // scores: lane t handles key offset t (t<21); slab row = sl + t
        float score = -1e30f;
        if (lane < WMAX && kvalid[sl + lane]) {
            float acc = 0.f;
            const float* kr = Ks[sl + lane];
            const float* qv = qs[w];
#pragma unroll
            for (int c = 0; c < 64; ++c) acc += qv[c] * kr[c];
            score = acc * 0.125f;  // 1/sqrt(C)
        }

        // softmax across the 21 window lanes
        float mx = score;
#pragma unroll
        for (int o = 16; o; o >>= 1) mx = fmaxf(mx, __shfl_xor_sync(0xffffffffu, mx, o));
        float e = (score > -1e29f) ? __expf(score - mx) : 0.f;
        float sm = e;
#pragma unroll
        for (int o = 16; o; o >>= 1) sm += __shfl_xor_sync(0xffffffffu, sm, o);
        ps[w][lane] = e / sm;
        __syncwarp();

        // output: each lane owns channels lane, lane+32
        float a0 = 0.f, a1 = 0.f;
#pragma unroll
        for (int t = 0; t < WMAX; ++t) {
            const float pt = ps[w][t];
            a0 += pt * Vs[sl + t][lane];
            a1 += pt * Vs[sl + t][lane + 32];
        }

        Att[base + lane]      = a0 * Gp[base + lane];
        Att[base + lane + 32] = a1 * Gp[base + lane + 32];
        __syncwarp();
    }
}

// ---------------------------------------------------------------------------
// kernel_launch: 4 projection GEMMs -> attention -> output GEMM
// Inputs (metadata order): Qin Kin Vin QTrans KTrans VTrans GW GB OW OB seqMask
// ---------------------------------------------------------------------------
extern "C" void kernel_launch(void* const* d_in, const int* in_sizes, int n_in,
                              void* d_out, int out_size)
{
    const float* Qin = (const float*)d_in[0];
    const float* Kin = (const float*)d_in[1];
    const float* Vin = (const float*)d_in[2];
    const float* QT  = (const float*)d_in[3];
    const float* KT  = (const float*)d_in[4];
    const float* VT  = (const float*)d_in[5];
    const float* GW  = (const float*)d_in[6];
    const float* GB  = (const float*)d_in[7];
    const float* OW  = (const float*)d_in[8];
    const float* OB  = (const float*)d_in[9];
    const unsigned char* seqMask = (const unsigned char*)d_in[10];
    float* out = (float*)d_out;

    dim3 gg(DD / 64, MROWS / 64);   // (4, 128) = 512 blocks
    sgemm64<<<gg, 256>>>(Qin, QT, nullptr, nullptr, -1, 0, 0);   // Qp
    sgemm64<<<gg, 256>>>(Kin, KT, nullptr, nullptr, -1, 1, 0);   // Kp
    sgemm64<<<gg, 256>>>(Vin, VT, nullptr, nullptr, -1, 2, 0);   // Vp
    sgemm64<<<gg, 256>>>(Vin, GW, GB,      nullptr, -1, 3, 1);   // Gp = sigmoid(Vin@GW+GB)
    attn_kernel<<<dim3(SS / 64, HH, BB), 256>>>(seqMask);        // Att = softmax*V*G
    sgemm64<<<gg, 256>>>(nullptr, OW, OB, out, 4, -1, 2);        // out = Att@OW+OB
}

// round 2
// speedup vs baseline: 2.4031x; 2.4031x over previous
#include <cuda_runtime.h>
#include <cuda_bf16.h>

// Problem constants
#define BB 4
#define SS 2048
#define HH 4
#define CC 64
#define DD 256          // H*C
#define WINR 10
#define WMAX 21         // 2*WINR+1
#define MROWS (BB*SS)   // 8192

// GEMM tiling
#define BM 128
#define BN 64
#define BK 32

// Scratch: 0=Qp 1=Kp 2=Vp 3=Gp 4=Att  (each [B*S, D] row-major)
__device__ float g_buf[5][MROWS * DD];

__device__ __forceinline__ unsigned f2tf(float x) {
    unsigned u;
    asm("cvt.rna.tf32.f32 %0, %1;" : "=r"(u) : "f"(x));
    return u;
}

__device__ __forceinline__ void mma8(float* d, const unsigned* a, const unsigned* b) {
    asm volatile(
        "mma.sync.aligned.m16n8k8.row.col.f32.tf32.tf32.f32 "
        "{%0,%1,%2,%3},{%4,%5,%6,%7},{%8,%9},{%0,%1,%2,%3};\n"
        : "+f"(d[0]), "+f"(d[1]), "+f"(d[2]), "+f"(d[3])
        : "r"(a[0]), "r"(a[1]), "r"(a[2]), "r"(a[3]), "r"(b[0]), "r"(b[1]));
}

// ---------------------------------------------------------------------------
// tf32 tensor-core GEMM core: C[M,DD] = A[M,DD] @ Bw[DD,DD]
// mode: 0 plain, 1 sigmoid(x+bias), 2 x+bias
// Smem banking: As stride 36 -> frag bank (4*gid+tig) bijective;
//               Bs stride 72 -> frag bank (8*tig+gid) bijective. uint4 STS.
// ---------------------------------------------------------------------------
__device__ __forceinline__ void gemm_core(const float* __restrict__ A,
                                          const float* __restrict__ Bw,
                                          const float* __restrict__ bias,
                                          float* __restrict__ C, int mode,
                                          unsigned (*As)[36], unsigned (*Bs)[72])
{
    const int tid = threadIdx.x;
    const int m0 = blockIdx.y * BM;
    const int n0 = blockIdx.x * BN;
    const int warp = tid >> 5, lane = tid & 31;
    const int wm = (warp & 3) * 32;   // warp m offset in tile
    const int wn = (warp >> 2) * 32;  // warp n offset in tile
    const int gid = lane >> 2, tig = lane & 3;

    float acc[2][4][4];
#pragma unroll
    for (int i = 0; i < 2; i++)
#pragma unroll
        for (int j = 0; j < 4; j++)
#pragma unroll
            for (int l = 0; l < 4; l++) acc[i][j][l] = 0.f;

    // global->shared load mapping (coalesced 128B per 8-lane group)
    const int ar  = tid >> 3;         // A row within tile (+32 per rep, 4 reps)
    const int afc = (tid & 7) * 4;    // A k-col (float4)
    const int bk  = tid >> 4;         // B k-row (+16 second rep)
    const int bn4 = (tid & 15) * 4;   // B n-col (float4)

    for (int k0 = 0; k0 < DD; k0 += BK) {
#pragma unroll
        for (int rep = 0; rep < 4; rep++) {
            const int r = ar + rep * 32;
            float4 v = *(const float4*)&A[(m0 + r) * DD + k0 + afc];
            uint4 u = make_uint4(f2tf(v.x), f2tf(v.y), f2tf(v.z), f2tf(v.w));
            *(uint4*)&As[r][afc] = u;
        }
#pragma unroll
        for (int rep = 0; rep < 2; rep++) {
            const int kr = bk + rep * 16;
            float4 v = *(const float4*)&Bw[(k0 + kr) * DD + n0 + bn4];
            uint4 u = make_uint4(f2tf(v.x), f2tf(v.y), f2tf(v.z), f2tf(v.w));
            *(uint4*)&Bs[kr][bn4] = u;
        }
        __syncthreads();

#pragma unroll
        for (int kk = 0; kk < BK; kk += 8) {
            unsigned a[2][4], b[4][2];
#pragma unroll
            for (int mt = 0; mt < 2; mt++) {
                const int r = wm + mt * 16 + gid;
                a[mt][0] = As[r][kk + tig];
                a[mt][1] = As[r + 8][kk + tig];
                a[mt][2] = As[r][kk + tig + 4];
                a[mt][3] = As[r + 8][kk + tig + 4];
            }
#pragma unroll
            for (int nt = 0; nt < 4; nt++) {
                const int cn = wn + nt * 8 + gid;
                b[nt][0] = Bs[kk + tig][cn];
                b[nt][1] = Bs[kk + tig + 4][cn];
            }
#pragma unroll
            for (int mt = 0; mt < 2; mt++)
#pragma unroll
                for (int nt = 0; nt < 4; nt++)
                    mma8(acc[mt][nt], a[mt], b[nt]);
        }
        __syncthreads();
    }

    // epilogue: c0 = C[gid][2*tig], c1 = +1, c2 = row+8
#pragma unroll
    for (int mt = 0; mt < 2; mt++) {
        const int r0 = m0 + wm + mt * 16 + gid;
#pragma unroll
        for (int nt = 0; nt < 4; nt++) {
            const int c0 = n0 + wn + nt * 8 + tig * 2;
            float v0 = acc[mt][nt][0], v1 = acc[mt][nt][1];
            float v2 = acc[mt][nt][2], v3 = acc[mt][nt][3];
            if (mode >= 1) {
                const float b0v = bias[c0], b1v = bias[c0 + 1];
                v0 += b0v; v1 += b1v; v2 += b0v; v3 += b1v;
            }
            if (mode == 1) {
                v0 = 1.f / (1.f + __expf(-v0));
                v1 = 1.f / (1.f + __expf(-v1));
                v2 = 1.f / (1.f + __expf(-v2));
                v3 = 1.f / (1.f + __expf(-v3));
            }
            *(float2*)&C[r0 * DD + c0] = make_float2(v0, v1);
            *(float2*)&C[(r0 + 8) * DD + c0] = make_float2(v2, v3);
        }
    }
}

// Fused projections: z=0 Qp, z=1 Kp, z=2 Vp, z=3 Gp=sigmoid(Vin@GW+GB)
__global__ void __launch_bounds__(256)
proj_kernel(const float* __restrict__ Qin, const float* __restrict__ Kin,
            const float* __restrict__ Vin, const float* __restrict__ QT,
            const float* __restrict__ KT, const float* __restrict__ VT,
            const float* __restrict__ GW, const float* __restrict__ GB)
{
    __shared__ unsigned As[BM][36];
    __shared__ unsigned Bs[BK][72];
    switch (blockIdx.z) {
        case 0:  gemm_core(Qin, QT, nullptr, g_buf[0], 0, As, Bs); break;
        case 1:  gemm_core(Kin, KT, nullptr, g_buf[1], 0, As, Bs); break;
        case 2:  gemm_core(Vin, VT, nullptr, g_buf[2], 0, As, Bs); break;
        default: gemm_core(Vin, GW, GB,      g_buf[3], 1, As, Bs); break;
    }
}

// Output projection: out = Att @ OW + OB
__global__ void __launch_bounds__(256)
out_kernel(const float* __restrict__ OW, const float* __restrict__ OB,
           float* __restrict__ out)
{
    __shared__ unsigned As[BM][36];
    __shared__ unsigned Bs[BK][72];
    gemm_core(g_buf[4], OW, OB, out, 2, As, Bs);
}

// ---------------------------------------------------------------------------
// Windowed attention + gating (unchanged from round 0).
// Block: 256 threads, handles (b, h, 64 consecutive queries).
// ---------------------------------------------------------------------------
__global__ void attn_kernel(const unsigned char* __restrict__ mask)
{
    __shared__ float Ks[84][65];
    __shared__ float Vs[84][65];
    __shared__ float qs[8][64];
    __shared__ float ps[8][32];
    __shared__ int   kvalid[84];

    const float* __restrict__ Qp = g_buf[0];
    const float* __restrict__ Kp = g_buf[1];
    const float* __restrict__ Vp = g_buf[2];
    const float* __restrict__ Gp = g_buf[3];
    float* __restrict__ Att = g_buf[4];

    const int s0 = blockIdx.x * 64;
    const int h  = blockIdx.y;
    const int b  = blockIdx.z;
    const int hb = h * CC;
    const int tid = threadIdx.x;

    for (int idx = tid; idx < 84 * 64; idx += 256) {
        const int r = idx >> 6;
        const int c = idx & 63;
        const int j = s0 - WINR + r;
        float kv = 0.f, vv = 0.f;
        if (j >= 0 && j < SS) {
            const int g = (b * SS + j) * DD + hb + c;
            kv = Kp[g];
            vv = Vp[g];
        }
        Ks[r][c] = kv;
        Vs[r][c] = vv;
    }
    if (tid < 84) {
        const int j = s0 - WINR + tid;
        kvalid[tid] = (j >= 0 && j < SS && mask[b * SS + j] == 0) ? 1 : 0;
    }
    __syncthreads();

    const int w = tid >> 5;
    const int lane = tid & 31;

    for (int i = 0; i < 8; ++i) {
        const int sl = w * 8 + i;          // local query index 0..63
        const int s = s0 + sl;
        const int base = (b * SS + s) * DD + hb;

        qs[w][lane]      = Qp[base + lane];
        qs[w][lane + 32] = Qp[base + lane + 32];
        __syncwarp();

        float score = -1e30f;
        if (lane < WMAX && kvalid[sl + lane]) {
            float acc = 0.f;
            const float* kr = Ks[sl + lane];
            const float* qv = qs[w];
#pragma unroll
            for (int c = 0; c < 64; ++c) acc += qv[c] * kr[c];
            score = acc * 0.125f;  // 1/sqrt(C)
        }

        float mx = score;
#pragma unroll
        for (int o = 16; o; o >>= 1) mx = fmaxf(mx, __shfl_xor_sync(0xffffffffu, mx, o));
        float e = (score > -1e29f) ? __expf(score - mx) : 0.f;
        float sm = e;
#pragma unroll
        for (int o = 16; o; o >>= 1) sm += __shfl_xor_sync(0xffffffffu, sm, o);
        ps[w][lane] = e / sm;
        __syncwarp();

        float a0 = 0.f, a1 = 0.f;
#pragma unroll
        for (int t = 0; t < WMAX; ++t) {
            const float pt = ps[w][t];
            a0 += pt * Vs[sl + t][lane];
            a1 += pt * Vs[sl + t][lane + 32];
        }

        Att[base + lane]      = a0 * Gp[base + lane];
        Att[base + lane + 32] = a1 * Gp[base + lane + 32];
        __syncwarp();
    }
}

// ---------------------------------------------------------------------------
// kernel_launch: fused projections -> attention -> output GEMM
// Inputs (metadata order): Qin Kin Vin QTrans KTrans VTrans GW GB OW OB seqMask
// ---------------------------------------------------------------------------
extern "C" void kernel_launch(void* const* d_in, const int* in_sizes, int n_in,
                              void* d_out, int out_size)
{
    const float* Qin = (const float*)d_in[0];
    const float* Kin = (const float*)d_in[1];
    const float* Vin = (const float*)d_in[2];
    const float* QT  = (const float*)d_in[3];
    const float* KT  = (const float*)d_in[4];
    const float* VT  = (const float*)d_in[5];
    const float* GW  = (const float*)d_in[6];
    const float* GB  = (const float*)d_in[7];
    const float* OW  = (const float*)d_in[8];
    const float* OB  = (const float*)d_in[9];
    const unsigned char* seqMask = (const unsigned char*)d_in[10];
    float* out = (float*)d_out;

    dim3 gproj(DD / BN, MROWS / BM, 4);   // (4, 64, 4) = 1024 blocks
    proj_kernel<<<gproj, 256>>>(Qin, Kin, Vin, QT, KT, VT, GW, GB);

    attn_kernel<<<dim3(SS / 64, HH, BB), 256>>>(seqMask);

    dim3 gout(DD / BN, MROWS / BM);       // (4, 64)
    out_kernel<<<gout, 256>>>(OW, OB, out);
}

// round 3
// speedup vs baseline: 2.4046x; 1.0007x over previous
#include <cuda_runtime.h>
#include <cuda_bf16.h>

// Problem constants
#define BB 4
#define SS 2048
#define HH 4
#define CC 64
#define DD 256          // H*C
#define WINR 10
#define WMAX 21         // 2*WINR+1
#define MROWS (BB*SS)   // 8192

// GEMM tiling
#define BM 128
#define BN 64
#define BK 32

// Scratch: 0=Qp 1=Kp 2=Vp 3=Gp 4=Att  (each [B*S, D] row-major)
__device__ float g_buf[5][MROWS * DD];

__device__ __forceinline__ unsigned f2tf(float x) {
    unsigned u;
    asm("cvt.rna.tf32.f32 %0, %1;" : "=r"(u) : "f"(x));
    return u;
}

__device__ __forceinline__ void mma8(float* d, const unsigned* a, const unsigned* b) {
    asm volatile(
        "mma.sync.aligned.m16n8k8.row.col.f32.tf32.tf32.f32 "
        "{%0,%1,%2,%3},{%4,%5,%6,%7},{%8,%9},{%0,%1,%2,%3};\n"
        : "+f"(d[0]), "+f"(d[1]), "+f"(d[2]), "+f"(d[3])
        : "r"(a[0]), "r"(a[1]), "r"(a[2]), "r"(a[3]), "r"(b[0]), "r"(b[1]));
}

// ---------------------------------------------------------------------------
// tf32 tensor-core GEMM core: C[M,DD] = A[M,DD] @ Bw[DD,DD]
// mode: 0 plain, 1 sigmoid(x+bias), 2 x+bias
// Smem banking: As stride 36 -> frag bank (4*gid+tig) bijective;
//               Bs stride 72 -> frag bank (8*tig+gid) bijective. uint4 STS.
// ---------------------------------------------------------------------------
__device__ __forceinline__ void gemm_core(const float* __restrict__ A,
                                          const float* __restrict__ Bw,
                                          const float* __restrict__ bias,
                                          float* __restrict__ C, int mode,
                                          unsigned (*As)[36], unsigned (*Bs)[72])
{
    const int tid = threadIdx.x;
    const int m0 = blockIdx.y * BM;
    const int n0 = blockIdx.x * BN;
    const int warp = tid >> 5, lane = tid & 31;
    const int wm = (warp & 3) * 32;   // warp m offset in tile
    const int wn = (warp >> 2) * 32;  // warp n offset in tile
    const int gid = lane >> 2, tig = lane & 3;

    float acc[2][4][4];
#pragma unroll
    for (int i = 0; i < 2; i++)
#pragma unroll
        for (int j = 0; j < 4; j++)
#pragma unroll
            for (int l = 0; l < 4; l++) acc[i][j][l] = 0.f;

    // global->shared load mapping (coalesced 128B per 8-lane group)
    const int ar  = tid >> 3;         // A row within tile (+32 per rep, 4 reps)
    const int afc = (tid & 7) * 4;    // A k-col (float4)
    const int bk  = tid >> 4;         // B k-row (+16 second rep)
    const int bn4 = (tid & 15) * 4;   // B n-col (float4)

    for (int k0 = 0; k0 < DD; k0 += BK) {
#pragma unroll
        for (int rep = 0; rep < 4; rep++) {
            const int r = ar + rep * 32;
            float4 v = *(const float4*)&A[(m0 + r) * DD + k0 + afc];
            uint4 u = make_uint4(f2tf(v.x), f2tf(v.y), f2tf(v.z), f2tf(v.w));
            *(uint4*)&As[r][afc] = u;
        }
#pragma unroll
        for (int rep = 0; rep < 2; rep++) {
            const int kr = bk + rep * 16;
            float4 v = *(const float4*)&Bw[(k0 + kr) * DD + n0 + bn4];
            uint4 u = make_uint4(f2tf(v.x), f2tf(v.y), f2tf(v.z), f2tf(v.w));
            *(uint4*)&Bs[kr][bn4] = u;
        }
        __syncthreads();

#pragma unroll
        for (int kk = 0; kk < BK; kk += 8) {
            unsigned a[2][4], b[4][2];
#pragma unroll
            for (int mt = 0; mt < 2; mt++) {
                const int r = wm + mt * 16 + gid;
                a[mt][0] = As[r][kk + tig];
                a[mt][1] = As[r + 8][kk + tig];
                a[mt][2] = As[r][kk + tig + 4];
                a[mt][3] = As[r + 8][kk + tig + 4];
            }
#pragma unroll
            for (int nt = 0; nt < 4; nt++) {
                const int cn = wn + nt * 8 + gid;
                b[nt][0] = Bs[kk + tig][cn];
                b[nt][1] = Bs[kk + tig + 4][cn];
            }
#pragma unroll
            for (int mt = 0; mt < 2; mt++)
#pragma unroll
                for (int nt = 0; nt < 4; nt++)
                    mma8(acc[mt][nt], a[mt], b[nt]);
        }
        __syncthreads();
    }

    // epilogue: c0 = C[gid][2*tig], c1 = +1, c2 = row+8
#pragma unroll
    for (int mt = 0; mt < 2; mt++) {
        const int r0 = m0 + wm + mt * 16 + gid;
#pragma unroll
        for (int nt = 0; nt < 4; nt++) {
            const int c0 = n0 + wn + nt * 8 + tig * 2;
            float v0 = acc[mt][nt][0], v1 = acc[mt][nt][1];
            float v2 = acc[mt][nt][2], v3 = acc[mt][nt][3];
            if (mode >= 1) {
                const float b0v = bias[c0], b1v = bias[c0 + 1];
                v0 += b0v; v1 += b1v; v2 += b0v; v3 += b1v;
            }
            if (mode == 1) {
                v0 = 1.f / (1.f + __expf(-v0));
                v1 = 1.f / (1.f + __expf(-v1));
                v2 = 1.f / (1.f + __expf(-v2));
                v3 = 1.f / (1.f + __expf(-v3));
            }
            *(float2*)&C[r0 * DD + c0] = make_float2(v0, v1);
            *(float2*)&C[(r0 + 8) * DD + c0] = make_float2(v2, v3);
        }
    }
}

// Fused projections: z=0 Qp, z=1 Kp, z=2 Vp, z=3 Gp=sigmoid(Vin@GW+GB)
__global__ void __launch_bounds__(256)
proj_kernel(const float* __restrict__ Qin, const float* __restrict__ Kin,
            const float* __restrict__ Vin, const float* __restrict__ QT,
            const float* __restrict__ KT, const float* __restrict__ VT,
            const float* __restrict__ GW, const float* __restrict__ GB)
{
    __shared__ unsigned As[BM][36];
    __shared__ unsigned Bs[BK][72];
    switch (blockIdx.z) {
        case 0:  gemm_core(Qin, QT, nullptr, g_buf[0], 0, As, Bs); break;
        case 1:  gemm_core(Kin, KT, nullptr, g_buf[1], 0, As, Bs); break;
        case 2:  gemm_core(Vin, VT, nullptr, g_buf[2], 0, As, Bs); break;
        default: gemm_core(Vin, GW, GB,      g_buf[3], 1, As, Bs); break;
    }
}

// Output projection: out = Att @ OW + OB
__global__ void __launch_bounds__(256)
out_kernel(const float* __restrict__ OW, const float* __restrict__ OB,
           float* __restrict__ out)
{
    __shared__ unsigned As[BM][36];
    __shared__ unsigned Bs[BK][72];
    gemm_core(g_buf[4], OW, OB, out, 2, As, Bs);
}

// ---------------------------------------------------------------------------
// Windowed attention + gating (unchanged from round 0).
// Block: 256 threads, handles (b, h, 64 consecutive queries).
// ---------------------------------------------------------------------------
__global__ void attn_kernel(const unsigned char* __restrict__ mask)
{
    __shared__ float Ks[84][65];
    __shared__ float Vs[84][65];
    __shared__ float qs[8][64];
    __shared__ float ps[8][32];
    __shared__ int   kvalid[84];

    const float* __restrict__ Qp = g_buf[0];
    const float* __restrict__ Kp = g_buf[1];
    const float* __restrict__ Vp = g_buf[2];
    const float* __restrict__ Gp = g_buf[3];
    float* __restrict__ Att = g_buf[4];

    const int s0 = blockIdx.x * 64;
    const int h  = blockIdx.y;
    const int b  = blockIdx.z;
    const int hb = h * CC;
    const int tid = threadIdx.x;

    for (int idx = tid; idx < 84 * 64; idx += 256) {
        const int r = idx >> 6;
        const int c = idx & 63;
        const int j = s0 - WINR + r;
        float kv = 0.f, vv = 0.f;
        if (j >= 0 && j < SS) {
            const int g = (b * SS + j) * DD + hb + c;
            kv = Kp[g];
            vv = Vp[g];
        }
        Ks[r][c] = kv;
        Vs[r][c] = vv;
    }
    if (tid < 84) {
        const int j = s0 - WINR + tid;
        kvalid[tid] = (j >= 0 && j < SS && mask[b * SS + j] == 0) ? 1 : 0;
    }
    __syncthreads();

    const int w = tid >> 5;
    const int lane = tid & 31;

    for (int i = 0; i < 8; ++i) {
        const int sl = w * 8 + i;          // local query index 0..63
        const int s = s0 + sl;
        const int base = (b * SS + s) * DD + hb;

        qs[w][lane]      = Qp[base + lane];
        qs[w][lane + 32] = Qp[base + lane + 32];
        __syncwarp();

        float score = -1e30f;
        if (lane < WMAX && kvalid[sl + lane]) {
            float acc = 0.f;
            const float* kr = Ks[sl + lane];
            const float* qv = qs[w];
#pragma unroll
            for (int c = 0; c < 64; ++c) acc += qv[c] * kr[c];
            score = acc * 0.125f;  // 1/sqrt(C)
        }

        float mx = score;
#pragma unroll
        for (int o = 16; o; o >>= 1) mx = fmaxf(mx, __shfl_xor_sync(0xffffffffu, mx, o));
        float e = (score > -1e29f) ? __expf(score - mx) : 0.f;
        float sm = e;
#pragma unroll
        for (int o = 16; o; o >>= 1) sm += __shfl_xor_sync(0xffffffffu, sm, o);
        ps[w][lane] = e / sm;
        __syncwarp();

        float a0 = 0.f, a1 = 0.f;
#pragma unroll
        for (int t = 0; t < WMAX; ++t) {
            const float pt = ps[w][t];
            a0 += pt * Vs[sl + t][lane];
            a1 += pt * Vs[sl + t][lane + 32];
        }

        Att[base + lane]      = a0 * Gp[base + lane];
        Att[base + lane + 32] = a1 * Gp[base + lane + 32];
        __syncwarp();
    }
}

// ---------------------------------------------------------------------------
// kernel_launch: fused projections -> attention -> output GEMM
// Inputs (metadata order): Qin Kin Vin QTrans KTrans VTrans GW GB OW OB seqMask
// ---------------------------------------------------------------------------
extern "C" void kernel_launch(void* const* d_in, const int* in_sizes, int n_in,
                              void* d_out, int out_size)
{
    const float* Qin = (const float*)d_in[0];
    const float* Kin = (const float*)d_in[1];
    const float* Vin = (const float*)d_in[2];
    const float* QT  = (const float*)d_in[3];
    const float* KT  = (const float*)d_in[4];
    const float* VT  = (const float*)d_in[5];
    const float* GW  = (const float*)d_in[6];
    const float* GB  = (const float*)d_in[7];
    const float* OW  = (const float*)d_in[8];
    const float* OB  = (const float*)d_in[9];
    const unsigned char* seqMask = (const unsigned char*)d_in[10];
    float* out = (float*)d_out;

    dim3 gproj(DD / BN, MROWS / BM, 4);   // (4, 64, 4) = 1024 blocks
    proj_kernel<<<gproj, 256>>>(Qin, Kin, Vin, QT, KT, VT, GW, GB);

    attn_kernel<<<dim3(SS / 64, HH, BB), 256>>>(seqMask);

    dim3 gout(DD / BN, MROWS / BM);       // (4, 64)
    out_kernel<<<gout, 256>>>(OW, OB, out);
}

// round 4
// speedup vs baseline: 2.4062x; 1.0007x over previous
#include <cuda_runtime.h>
#include <cuda_bf16.h>

// Problem constants
#define BB 4
#define SS 2048
#define HH 4
#define CC 64
#define DD 256          // H*C
#define WINR 10
#define WMAX 21         // 2*WINR+1
#define MROWS (BB*SS)   // 8192

// GEMM tiling
#define BM 128
#define BN 64
#define BK 32

// Scratch: 0=Qp 1=Kp 2=Vp 3=Gp 4=Att  (each [B*S, D] row-major)
__device__ float g_buf[5][MROWS * DD];

__device__ __forceinline__ unsigned f2tf(float x) {
    unsigned u;
    asm("cvt.rna.tf32.f32 %0, %1;" : "=r"(u) : "f"(x));
    return u;
}

__device__ __forceinline__ void mma8(float* d, const unsigned* a, const unsigned* b) {
    asm volatile(
        "mma.sync.aligned.m16n8k8.row.col.f32.tf32.tf32.f32 "
        "{%0,%1,%2,%3},{%4,%5,%6,%7},{%8,%9},{%0,%1,%2,%3};\n"
        : "+f"(d[0]), "+f"(d[1]), "+f"(d[2]), "+f"(d[3])
        : "r"(a[0]), "r"(a[1]), "r"(a[2]), "r"(a[3]), "r"(b[0]), "r"(b[1]));
}

// ---------------------------------------------------------------------------
// tf32 tensor-core GEMM core: C[M,DD] = A[M,DD] @ Bw[DD,DD]
// mode: 0 plain, 1 sigmoid(x+bias), 2 x+bias
// Smem banking: As stride 36 -> frag bank (4*gid+tig) bijective;
//               Bs stride 72 -> frag bank (8*tig+gid) bijective. uint4 STS.
// ---------------------------------------------------------------------------
__device__ __forceinline__ void gemm_core(const float* __restrict__ A,
                                          const float* __restrict__ Bw,
                                          const float* __restrict__ bias,
                                          float* __restrict__ C, int mode,
                                          unsigned (*As)[36], unsigned (*Bs)[72])
{
    const int tid = threadIdx.x;
    const int m0 = blockIdx.y * BM;
    const int n0 = blockIdx.x * BN;
    const int warp = tid >> 5, lane = tid & 31;
    const int wm = (warp & 3) * 32;   // warp m offset in tile
    const int wn = (warp >> 2) * 32;  // warp n offset in tile
    const int gid = lane >> 2, tig = lane & 3;

    float acc[2][4][4];
#pragma unroll
    for (int i = 0; i < 2; i++)
#pragma unroll
        for (int j = 0; j < 4; j++)
#pragma unroll
            for (int l = 0; l < 4; l++) acc[i][j][l] = 0.f;

    // global->shared load mapping (coalesced 128B per 8-lane group)
    const int ar  = tid >> 3;         // A row within tile (+32 per rep, 4 reps)
    const int afc = (tid & 7) * 4;    // A k-col (float4)
    const int bk  = tid >> 4;         // B k-row (+16 second rep)
    const int bn4 = (tid & 15) * 4;   // B n-col (float4)

    for (int k0 = 0; k0 < DD; k0 += BK) {
#pragma unroll
        for (int rep = 0; rep < 4; rep++) {
            const int r = ar + rep * 32;
            float4 v = *(const float4*)&A[(m0 + r) * DD + k0 + afc];
            uint4 u = make_uint4(f2tf(v.x), f2tf(v.y), f2tf(v.z), f2tf(v.w));
            *(uint4*)&As[r][afc] = u;
        }
#pragma unroll
        for (int rep = 0; rep < 2; rep++) {
            const int kr = bk + rep * 16;
            float4 v = *(const float4*)&Bw[(k0 + kr) * DD + n0 + bn4];
            uint4 u = make_uint4(f2tf(v.x), f2tf(v.y), f2tf(v.z), f2tf(v.w));
            *(uint4*)&Bs[kr][bn4] = u;
        }
        __syncthreads();

#pragma unroll
        for (int kk = 0; kk < BK; kk += 8) {
            unsigned a[2][4], b[4][2];
#pragma unroll
            for (int mt = 0; mt < 2; mt++) {
                const int r = wm + mt * 16 + gid;
                a[mt][0] = As[r][kk + tig];
                a[mt][1] = As[r + 8][kk + tig];
                a[mt][2] = As[r][kk + tig + 4];
                a[mt][3] = As[r + 8][kk + tig + 4];
            }
#pragma unroll
            for (int nt = 0; nt < 4; nt++) {
                const int cn = wn + nt * 8 + gid;
                b[nt][0] = Bs[kk + tig][cn];
                b[nt][1] = Bs[kk + tig + 4][cn];
            }
#pragma unroll
            for (int mt = 0; mt < 2; mt++)
#pragma unroll
                for (int nt = 0; nt < 4; nt++)
                    mma8(acc[mt][nt], a[mt], b[nt]);
        }
        __syncthreads();
    }

    // epilogue: c0 = C[gid][2*tig], c1 = +1, c2 = row+8
#pragma unroll
    for (int mt = 0; mt < 2; mt++) {
        const int r0 = m0 + wm + mt * 16 + gid;
#pragma unroll
        for (int nt = 0; nt < 4; nt++) {
            const int c0 = n0 + wn + nt * 8 + tig * 2;
            float v0 = acc[mt][nt][0], v1 = acc[mt][nt][1];
            float v2 = acc[mt][nt][2], v3 = acc[mt][nt][3];
            if (mode >= 1) {
                const float b0v = bias[c0], b1v = bias[c0 + 1];
                v0 += b0v; v1 += b1v; v2 += b0v; v3 += b1v;
            }
            if (mode == 1) {
                v0 = 1.f / (1.f + __expf(-v0));
                v1 = 1.f / (1.f + __expf(-v1));
                v2 = 1.f / (1.f + __expf(-v2));
                v3 = 1.f / (1.f + __expf(-v3));
            }
            *(float2*)&C[r0 * DD + c0] = make_float2(v0, v1);
            *(float2*)&C[(r0 + 8) * DD + c0] = make_float2(v2, v3);
        }
    }
}

// Fused projections: z=0 Qp, z=1 Kp, z=2 Vp, z=3 Gp=sigmoid(Vin@GW+GB)
__global__ void __launch_bounds__(256)
proj_kernel(const float* __restrict__ Qin, const float* __restrict__ Kin,
            const float* __restrict__ Vin, const float* __restrict__ QT,
            const float* __restrict__ KT, const float* __restrict__ VT,
            const float* __restrict__ GW, const float* __restrict__ GB)
{
    __shared__ unsigned As[BM][36];
    __shared__ unsigned Bs[BK][72];
    switch (blockIdx.z) {
        case 0:  gemm_core(Qin, QT, nullptr, g_buf[0], 0, As, Bs); break;
        case 1:  gemm_core(Kin, KT, nullptr, g_buf[1], 0, As, Bs); break;
        case 2:  gemm_core(Vin, VT, nullptr, g_buf[2], 0, As, Bs); break;
        default: gemm_core(Vin, GW, GB,      g_buf[3], 1, As, Bs); break;
    }
}

// Output projection: out = Att @ OW + OB
__global__ void __launch_bounds__(256)
out_kernel(const float* __restrict__ OW, const float* __restrict__ OB,
           float* __restrict__ out)
{
    __shared__ unsigned As[BM][36];
    __shared__ unsigned Bs[BK][72];
    gemm_core(g_buf[4], OW, OB, out, 2, As, Bs);
}

// ---------------------------------------------------------------------------
// Windowed attention + gating (unchanged from round 0).
// Block: 256 threads, handles (b, h, 64 consecutive queries).
// ---------------------------------------------------------------------------
__global__ void attn_kernel(const unsigned char* __restrict__ mask)
{
    __shared__ float Ks[84][65];
    __shared__ float Vs[84][65];
    __shared__ float qs[8][64];
    __shared__ float ps[8][32];
    __shared__ int   kvalid[84];

    const float* __restrict__ Qp = g_buf[0];
    const float* __restrict__ Kp = g_buf[1];
    const float* __restrict__ Vp = g_buf[2];
    const float* __restrict__ Gp = g_buf[3];
    float* __restrict__ Att = g_buf[4];

    const int s0 = blockIdx.x * 64;
    const int h  = blockIdx.y;
    const int b  = blockIdx.z;
    const int hb = h * CC;
    const int tid = threadIdx.x;

    for (int idx = tid; idx < 84 * 64; idx += 256) {
        const int r = idx >> 6;
        const int c = idx & 63;
        const int j = s0 - WINR + r;
        float kv = 0.f, vv = 0.f;
        if (j >= 0 && j < SS) {
            const int g = (b * SS + j) * DD + hb + c;
            kv = Kp[g];
            vv = Vp[g];
        }
        Ks[r][c] = kv;
        Vs[r][c] = vv;
    }
    if (tid < 84) {
        const int j = s0 - WINR + tid;
        kvalid[tid] = (j >= 0 && j < SS && mask[b * SS + j] == 0) ? 1 : 0;
    }
    __syncthreads();

    const int w = tid >> 5;
    const int lane = tid & 31;

    for (int i = 0; i < 8; ++i) {
        const int sl = w * 8 + i;          // local query index 0..63
        const int s = s0 + sl;
        const int base = (b * SS + s) * DD + hb;

        qs[w][lane]      = Qp[base + lane];
        qs[w][lane + 32] = Qp[base + lane + 32];
        __syncwarp();

        float score = -1e30f;
        if (lane < WMAX && kvalid[sl + lane]) {
            float acc = 0.f;
            const float* kr = Ks[sl + lane];
            const float* qv = qs[w];
#pragma unroll
            for (int c = 0; c < 64; ++c) acc += qv[c] * kr[c];
            score = acc * 0.125f;  // 1/sqrt(C)
        }

        float mx = score;
#pragma unroll
        for (int o = 16; o; o >>= 1) mx = fmaxf(mx, __shfl_xor_sync(0xffffffffu, mx, o));
        float e = (score > -1e29f) ? __expf(score - mx) : 0.f;
        float sm = e;
#pragma unroll
        for (int o = 16; o; o >>= 1) sm += __shfl_xor_sync(0xffffffffu, sm, o);
        ps[w][lane] = e / sm;
        __syncwarp();

        float a0 = 0.f, a1 = 0.f;
#pragma unroll
        for (int t = 0; t < WMAX; ++t) {
            const float pt = ps[w][t];
            a0 += pt * Vs[sl + t][lane];
            a1 += pt * Vs[sl + t][lane + 32];
        }

        Att[base + lane]      = a0 * Gp[base + lane];
        Att[base + lane + 32] = a1 * Gp[base + lane + 32];
        __syncwarp();
    }
}

// ---------------------------------------------------------------------------
// kernel_launch: fused projections -> attention -> output GEMM
// Inputs (metadata order): Qin Kin Vin QTrans KTrans VTrans GW GB OW OB seqMask
// ---------------------------------------------------------------------------
extern "C" void kernel_launch(void* const* d_in, const int* in_sizes, int n_in,
                              void* d_out, int out_size)
{
    const float* Qin = (const float*)d_in[0];
    const float* Kin = (const float*)d_in[1];
    const float* Vin = (const float*)d_in[2];
    const float* QT  = (const float*)d_in[3];
    const float* KT  = (const float*)d_in[4];
    const float* VT  = (const float*)d_in[5];
    const float* GW  = (const float*)d_in[6];
    const float* GB  = (const float*)d_in[7];
    const float* OW  = (const float*)d_in[8];
    const float* OB  = (const float*)d_in[9];
    const unsigned char* seqMask = (const unsigned char*)d_in[10];
    float* out = (float*)d_out;

    dim3 gproj(DD / BN, MROWS / BM, 4);   // (4, 64, 4) = 1024 blocks
    proj_kernel<<<gproj, 256>>>(Qin, Kin, Vin, QT, KT, VT, GW, GB);

    attn_kernel<<<dim3(SS / 64, HH, BB), 256>>>(seqMask);

    dim3 gout(DD / BN, MROWS / BM);       // (4, 64)
    out_kernel<<<gout, 256>>>(OW, OB, out);
}